// round 2
// baseline (speedup 1.0000x reference)
#include <cuda_runtime.h>
#include <cuda_bf16.h>

// Problem constants
#define Bn 4
#define Cn 64
#define Hn 96
#define Wn 96
#define PLANE (Hn*Wn)            // 9216
#define NPLANES (Bn*Cn)          // 256
#define NTOT (NPLANES*PLANE)     // 2359296
#define CNT_PER_CH (Bn*PLANE)    // 36864
#define BN_EPS 1e-5f
#define NPART 36                 // partial sums per channel: Bn * (3x3 blocks)

// Scratch (__device__ globals; allocation-free rule)
__device__ float g_y[NTOT];
__device__ float g_psum[Cn * NPART];
__device__ float g_psq [Cn * NPART];

// ---------------------------------------------------------------------------
// Kernel 1: fused KAN depthwise conv + race-free per-channel partial sums
// grid = (3, 3, 256 planes), block = 256 threads (32 x 8)
// Each thread computes a vertical strip of 4 consecutive output rows with a
// sliding 3x3 register window over the transformed tile.
// ---------------------------------------------------------------------------
__global__ __launch_bounds__(256, 2)
void kan_conv_kernel(const float* __restrict__ x,
                     const float* __restrict__ base_weight,    // (9)
                     const float* __restrict__ spline_weight,  // (9,8)
                     const float* __restrict__ spline_scaler)  // (9)
{
    __shared__ float2 s_su[34 * 34];     // (silu, u) per tile element
    __shared__ int    s_mo[34 * 34];     // coef-row byte offset m*144
    __shared__ float4 s_coef[12 * 9];    // cubic coeffs per (interval m, tap k)
    __shared__ float  s_bw[9];
    __shared__ float  s_rs[8], s_rq[8];

    const int tid   = threadIdx.x;
    const int plane = blockIdx.z;
    const int ty0   = blockIdx.y * 32;
    const int tx0   = blockIdx.x * 32;

    // ---- build coefficient table (uniform cubic B-spline, closed form) ----
    if (tid < 108) {
        const int m = tid / 9, k = tid % 9;
        float c0 = 0.f, c1 = 0.f, c2 = 0.f, c3 = 0.f;
        if (m < 11) {
            const float F[4][4] = {
                {1.f, -3.f,  3.f, -1.f},   // N_{m-3}
                {4.f,  0.f, -6.f,  3.f},   // N_{m-2}
                {1.f,  3.f,  3.f, -3.f},   // N_{m-1}
                {0.f,  0.f,  0.f,  1.f}    // N_{m}
            };
            const float sc = spline_scaler[k];
            #pragma unroll
            for (int r = 0; r < 4; r++) {
                int j = m - 3 + r;
                if (j >= 0 && j < 8) {
                    float w = spline_weight[k * 8 + j] * sc;
                    c0 += w * F[r][0]; c1 += w * F[r][1];
                    c2 += w * F[r][2]; c3 += w * F[r][3];
                }
            }
        }
        const float inv6 = 1.0f / 6.0f;
        s_coef[m * 9 + k] = make_float4(c0 * inv6, c1 * inv6, c2 * inv6, c3 * inv6);
    }
    if (tid < 9) s_bw[tid] = base_weight[tid];

    // ---- load + transform halo tile (34x34), zero-padded outside plane ----
    const float* xp = x + plane * PLANE;
    for (int i = tid; i < 34 * 34; i += 256) {
        int hy = i / 34, hx = i % 34;
        int gy = ty0 + hy - 1, gx = tx0 + hx - 1;
        float v = (gy >= 0 && gy < Hn && gx >= 0 && gx < Wn) ? xp[gy * Wn + gx] : 0.0f;
        float s  = __fdividef(v, 1.0f + __expf(-v));   // silu
        float mu = (v + 2.2f) * 2.5f;                  // (x - t0)/h
        if (!(mu >= 0.0f && mu < 11.0f)) mu = 11.0f;   // sentinel -> zero row
        int   m = (int)mu;
        float u = mu - (float)m;
        s_su[i] = make_float2(s, u);
        s_mo[i] = m * 144;                             // byte offset of coef row
    }
    __syncthreads();

    float bw[9];
    #pragma unroll
    for (int k = 0; k < 9; k++) bw[k] = s_bw[k];

    const char* cbase = (const char*)s_coef;

    // ---- compute strip of 4 consecutive rows per thread ----
    const int tx  = tid & 31;
    const int tyb = tid >> 5;
    const int oy0 = tyb * 4;                // output row base within 32-row tile
    float lsum = 0.f, lsq = 0.f;

    float2 su[3][3];
    int    mo[3][3];

    // preload window rows: tile rows oy0, oy0+1 (output row oy uses tile rows oy..oy+2)
    #pragma unroll
    for (int s = 0; s < 2; s++) {
        #pragma unroll
        for (int dx = 0; dx < 3; dx++) {
            int idx = (oy0 + s) * 34 + tx + dx;
            su[s][dx] = s_su[idx];
            mo[s][dx] = s_mo[idx];
        }
    }

    #pragma unroll
    for (int r = 0; r < 4; r++) {
        // load next row into slot (r+2)%3
        {
            const int sl = (r + 2) % 3;
            #pragma unroll
            for (int dx = 0; dx < 3; dx++) {
                int idx = (oy0 + r + 2) * 34 + tx + dx;
                su[sl][dx] = s_su[idx];
                mo[sl][dx] = s_mo[idx];
            }
        }

        float acc = 0.f;
        #pragma unroll
        for (int dy = 0; dy < 3; dy++) {
            const int sl = (r + dy) % 3;
            #pragma unroll
            for (int dx = 0; dx < 3; dx++) {
                const int k = dy * 3 + dx;
                const float4* cp = (const float4*)(cbase + mo[sl][dx]);
                float4 cf = cp[k];
                float2 t  = su[sl][dx];
                float poly = fmaf(t.y, fmaf(t.y, fmaf(t.y, cf.w, cf.z), cf.y), cf.x);
                acc += poly + bw[k] * t.x;
            }
        }

        g_y[plane * PLANE + (ty0 + oy0 + r) * Wn + (tx0 + tx)] = acc;
        lsum += acc;
        lsq  = fmaf(acc, acc, lsq);
    }

    // ---- block reduction -> race-free partial slot (no atomics, no zeroing) ----
    #pragma unroll
    for (int o = 16; o > 0; o >>= 1) {
        lsum += __shfl_down_sync(0xffffffffu, lsum, o);
        lsq  += __shfl_down_sync(0xffffffffu, lsq,  o);
    }
    if (tx == 0) { s_rs[tyb] = lsum; s_rq[tyb] = lsq; }
    __syncthreads();
    if (tid == 0) {
        float s = 0.f, q = 0.f;
        #pragma unroll
        for (int i = 0; i < 8; i++) { s += s_rs[i]; q += s_rq[i]; }
        const int c = plane & (Cn - 1);
        const int b = plane >> 6;
        const int slot = c * NPART + b * 9 + blockIdx.y * 3 + blockIdx.x;
        g_psum[slot] = s;
        g_psq [slot] = q;
    }
}

// ---------------------------------------------------------------------------
// Kernel 2: BatchNorm (batch stats from partials) + ReLU, float4 vectorized
// grid = 256 planes, block = 256 threads
// ---------------------------------------------------------------------------
__global__ __launch_bounds__(256)
void bn_relu_kernel(const float* __restrict__ gamma,
                    const float* __restrict__ beta,
                    float* __restrict__ out)
{
    __shared__ float s_p[2];
    const int plane = blockIdx.x;
    const int c     = plane & (Cn - 1);
    const int tid   = threadIdx.x;

    if (tid < 32) {
        float s = 0.f, q = 0.f;
        for (int j = tid; j < NPART; j += 32) {
            s += g_psum[c * NPART + j];
            q += g_psq [c * NPART + j];
        }
        #pragma unroll
        for (int o = 16; o > 0; o >>= 1) {
            s += __shfl_down_sync(0xffffffffu, s, o);
            q += __shfl_down_sync(0xffffffffu, q, o);
        }
        if (tid == 0) {
            const float invN = 1.0f / (float)CNT_PER_CH;
            float mean = s * invN;
            float var  = q * invN - mean * mean;
            float scl  = rsqrtf(var + BN_EPS) * gamma[c];
            s_p[0] = scl;
            s_p[1] = fmaf(-mean, scl, beta[c]);
        }
    }
    __syncthreads();

    const float scl = s_p[0], sh = s_p[1];
    const float4* yv = (const float4*)g_y + plane * (PLANE / 4);
    float4*       ov = (float4*)out      + plane * (PLANE / 4);

    #pragma unroll
    for (int j = 0; j < (PLANE / 4) / 256; j++) {
        int i = tid + j * 256;
        float4 v = yv[i];
        float4 o;
        o.x = fmaxf(fmaf(v.x, scl, sh), 0.0f);
        o.y = fmaxf(fmaf(v.y, scl, sh), 0.0f);
        o.z = fmaxf(fmaf(v.z, scl, sh), 0.0f);
        o.w = fmaxf(fmaf(v.w, scl, sh), 0.0f);
        ov[i] = o;
    }
}

// ---------------------------------------------------------------------------
extern "C" void kernel_launch(void* const* d_in, const int* in_sizes, int n_in,
                              void* d_out, int out_size)
{
    const float* x             = (const float*)d_in[0];
    const float* base_weight   = (const float*)d_in[1];
    const float* spline_weight = (const float*)d_in[2];
    const float* spline_scaler = (const float*)d_in[3];
    const float* bn_gamma      = (const float*)d_in[4];
    const float* bn_beta       = (const float*)d_in[5];
    float* out                 = (float*)d_out;

    dim3 grid(3, 3, NPLANES);
    kan_conv_kernel<<<grid, 256>>>(x, base_weight, spline_weight, spline_scaler);

    bn_relu_kernel<<<NPLANES, 256>>>(bn_gamma, bn_beta, out);
}

// round 3
// speedup vs baseline: 1.1476x; 1.1476x over previous
#include <cuda_runtime.h>
#include <cuda_bf16.h>

// Problem constants
#define Bn 4
#define Cn 64
#define Hn 96
#define Wn 96
#define PLANE (Hn*Wn)            // 9216
#define NPLANES (Bn*Cn)          // 256
#define NTOT (NPLANES*PLANE)     // 2359296
#define CNT_PER_CH (Bn*PLANE)    // 36864
#define BN_EPS 1e-5f
#define NPART 36                 // partial sums per channel: Bn * (3x3 blocks)

// Scratch (__device__ globals; allocation-free rule)
__device__ float g_y[NTOT];
__device__ float g_psum[Cn * NPART];
__device__ float g_psq [Cn * NPART];

// transform: silu(x) and packed spline coordinate mu = m + u
__device__ __forceinline__ float2 kan_transform(float x) {
    float s = __fdividef(x, 1.0f + __expf(-x));   // silu
    float mu = (x + 2.2f) * 2.5f;                 // (x - t0)/h, t0=-2.2, h=0.4
    if (!(mu >= 0.0f && mu < 11.0f)) mu = 11.0f;  // sentinel row -> zero coeffs
    return make_float2(s, mu);
}

// ---------------------------------------------------------------------------
// Kernel 1: fused KAN depthwise conv + race-free per-channel partial sums
// grid = (3, 3, 256 planes), block = 256 threads (32 x 8), 4 rows/thread
// (R1 inner loop — proven fastest — with no-atomic partial-sum epilogue)
// ---------------------------------------------------------------------------
__global__ __launch_bounds__(256)
void kan_conv_kernel(const float* __restrict__ x,
                     const float* __restrict__ base_weight,    // (9)
                     const float* __restrict__ spline_weight,  // (9,8)
                     const float* __restrict__ spline_scaler)  // (9)
{
    __shared__ float2 s_t[34 * 35];      // (silu, mu) tile with halo, pitch 35
    __shared__ float4 s_coef[12 * 9];    // cubic coeffs per (interval m, tap k)
    __shared__ float  s_bw[9];
    __shared__ float  s_rs[8], s_rq[8];

    const int tid   = threadIdx.x;
    const int plane = blockIdx.z;
    const int ty0   = blockIdx.y * 32;
    const int tx0   = blockIdx.x * 32;

    // ---- build coefficient table (uniform cubic B-spline, closed form) ----
    if (tid < 108) {
        const int m = tid / 9, k = tid % 9;
        float c0 = 0.f, c1 = 0.f, c2 = 0.f, c3 = 0.f;
        if (m < 11) {
            const float F[4][4] = {
                {1.f, -3.f,  3.f, -1.f},   // N_{m-3}
                {4.f,  0.f, -6.f,  3.f},   // N_{m-2}
                {1.f,  3.f,  3.f, -3.f},   // N_{m-1}
                {0.f,  0.f,  0.f,  1.f}    // N_{m}
            };
            const float sc = spline_scaler[k];
            #pragma unroll
            for (int r = 0; r < 4; r++) {
                int j = m - 3 + r;
                if (j >= 0 && j < 8) {
                    float w = spline_weight[k * 8 + j] * sc;
                    c0 += w * F[r][0]; c1 += w * F[r][1];
                    c2 += w * F[r][2]; c3 += w * F[r][3];
                }
            }
        }
        const float inv6 = 1.0f / 6.0f;
        s_coef[m * 9 + k] = make_float4(c0 * inv6, c1 * inv6, c2 * inv6, c3 * inv6);
    }
    if (tid < 9) s_bw[tid] = base_weight[tid];

    // ---- load + transform halo tile (34x34), zero-padded outside plane ----
    const float* xp = x + plane * PLANE;
    for (int i = tid; i < 34 * 34; i += 256) {
        int hy = i / 34, hx = i % 34;
        int gy = ty0 + hy - 1, gx = tx0 + hx - 1;
        float v = (gy >= 0 && gy < Hn && gx >= 0 && gx < Wn) ? xp[gy * Wn + gx] : 0.0f;
        s_t[hy * 35 + hx] = kan_transform(v);
    }
    __syncthreads();

    // ---- compute 32x32 outputs (4 strided rows per thread) ----
    const int tx  = tid & 31;
    const int tyb = tid >> 5;
    float lsum = 0.f, lsq = 0.f;

    #pragma unroll
    for (int r = 0; r < 4; r++) {
        const int oy = tyb + r * 8;
        float acc = 0.f;
        #pragma unroll
        for (int dy = 0; dy < 3; dy++) {
            #pragma unroll
            for (int dx = 0; dx < 3; dx++) {
                const int k = dy * 3 + dx;
                float2 t = s_t[(oy + dy) * 35 + (tx + dx)];
                int   m = (int)t.y;
                float u = t.y - (float)m;
                float4 cf = s_coef[m * 9 + k];
                float poly = fmaf(u, fmaf(u, fmaf(u, cf.w, cf.z), cf.y), cf.x);
                acc += poly + s_bw[k] * t.x;
            }
        }
        g_y[plane * PLANE + (ty0 + oy) * Wn + (tx0 + tx)] = acc;
        lsum += acc;
        lsq  = fmaf(acc, acc, lsq);
    }

    // ---- block reduction -> race-free partial slot (no atomics, no zeroing) ----
    #pragma unroll
    for (int o = 16; o > 0; o >>= 1) {
        lsum += __shfl_down_sync(0xffffffffu, lsum, o);
        lsq  += __shfl_down_sync(0xffffffffu, lsq,  o);
    }
    if (tx == 0) { s_rs[tyb] = lsum; s_rq[tyb] = lsq; }
    __syncthreads();
    if (tid == 0) {
        float s = 0.f, q = 0.f;
        #pragma unroll
        for (int i = 0; i < 8; i++) { s += s_rs[i]; q += s_rq[i]; }
        const int c = plane & (Cn - 1);
        const int b = plane >> 6;
        const int slot = c * NPART + b * 9 + blockIdx.y * 3 + blockIdx.x;
        g_psum[slot] = s;
        g_psq [slot] = q;
    }
}

// ---------------------------------------------------------------------------
// Kernel 2: BatchNorm (batch stats from partials) + ReLU
// grid = (9 chunks, 256 planes), block = 256; one float4 per thread -> high TLP
// ---------------------------------------------------------------------------
__global__ __launch_bounds__(256)
void bn_relu_kernel(const float* __restrict__ gamma,
                    const float* __restrict__ beta,
                    float* __restrict__ out)
{
    __shared__ float s_p[2];
    const int plane = blockIdx.y;
    const int c     = plane & (Cn - 1);
    const int tid   = threadIdx.x;

    // issue the data load immediately (independent of the stats reduction)
    const int i = blockIdx.x * 256 + tid;                 // float4 idx in plane
    float4 v = reinterpret_cast<const float4*>(g_y)[plane * (PLANE / 4) + i];

    if (tid < 32) {
        float s = 0.f, q = 0.f;
        #pragma unroll
        for (int j = tid; j < NPART; j += 32) {
            s += g_psum[c * NPART + j];
            q += g_psq [c * NPART + j];
        }
        #pragma unroll
        for (int o = 16; o > 0; o >>= 1) {
            s += __shfl_down_sync(0xffffffffu, s, o);
            q += __shfl_down_sync(0xffffffffu, q, o);
        }
        if (tid == 0) {
            const float invN = 1.0f / (float)CNT_PER_CH;
            float mean = s * invN;
            float var  = q * invN - mean * mean;
            float scl  = rsqrtf(var + BN_EPS) * gamma[c];
            s_p[0] = scl;
            s_p[1] = fmaf(-mean, scl, beta[c]);
        }
    }
    __syncthreads();

    const float scl = s_p[0], sh = s_p[1];
    float4 o;
    o.x = fmaxf(fmaf(v.x, scl, sh), 0.0f);
    o.y = fmaxf(fmaf(v.y, scl, sh), 0.0f);
    o.z = fmaxf(fmaf(v.z, scl, sh), 0.0f);
    o.w = fmaxf(fmaf(v.w, scl, sh), 0.0f);
    reinterpret_cast<float4*>(out)[plane * (PLANE / 4) + i] = o;
}

// ---------------------------------------------------------------------------
extern "C" void kernel_launch(void* const* d_in, const int* in_sizes, int n_in,
                              void* d_out, int out_size)
{
    const float* x             = (const float*)d_in[0];
    const float* base_weight   = (const float*)d_in[1];
    const float* spline_weight = (const float*)d_in[2];
    const float* spline_scaler = (const float*)d_in[3];
    const float* bn_gamma      = (const float*)d_in[4];
    const float* bn_beta       = (const float*)d_in[5];
    float* out                 = (float*)d_out;

    dim3 grid(3, 3, NPLANES);
    kan_conv_kernel<<<grid, 256>>>(x, base_weight, spline_weight, spline_scaler);

    dim3 bgrid(PLANE / 4 / 256, NPLANES);   // (9, 256)
    bn_relu_kernel<<<bgrid, 256>>>(bn_gamma, bn_beta, out);
}

// round 4
// speedup vs baseline: 1.3957x; 1.2162x over previous
#include <cuda_runtime.h>
#include <cuda_fp16.h>
#include <cuda_bf16.h>

// Problem constants
#define Bn 4
#define Cn 64
#define Hn 96
#define Wn 96
#define PLANE (Hn*Wn)            // 9216
#define NPLANES (Bn*Cn)          // 256
#define NTOT (NPLANES*PLANE)     // 2359296
#define CNT_PER_CH (Bn*PLANE)    // 36864
#define BN_EPS 1e-5f
#define NPART 36                 // partial sums per channel: Bn * (3x3 blocks)

// Scratch (__device__ globals; allocation-free rule)
__device__ float g_y[NTOT];
__device__ float g_psum[Cn * NPART];
__device__ float g_psq [Cn * NPART];

// transform: silu(x) and packed spline coordinate mu = m + u
__device__ __forceinline__ float2 kan_transform(float x) {
    float s = __fdividef(x, 1.0f + __expf(-x));   // silu
    float mu = (x + 2.2f) * 2.5f;                 // (x - t0)/h, t0=-2.2, h=0.4
    if (!(mu >= 0.0f && mu < 11.0f)) mu = 11.0f;  // sentinel row -> zero coeffs
    return make_float2(s, mu);
}

// ---------------------------------------------------------------------------
// Kernel 1: fused KAN depthwise conv + race-free per-channel partial sums
// grid = (3, 3, 256 planes), block = 256 threads (32 x 8), 4 rows/thread.
// Coefficient table stored as fp16 (8B gather instead of 16B) — the smem
// crossbar on this gather is the kernel's bottleneck.
// ---------------------------------------------------------------------------
__global__ __launch_bounds__(256)
void kan_conv_kernel(const float* __restrict__ x,
                     const float* __restrict__ base_weight,    // (9)
                     const float* __restrict__ spline_weight,  // (9,8)
                     const float* __restrict__ spline_scaler)  // (9)
{
    __shared__ float2 s_t[34 * 35];        // (silu, mu) tile with halo, pitch 35
    __shared__ uint2  s_coef[12 * 9];      // half2(c0,c1), half2(c2,c3)
    __shared__ float  s_bw[9];
    __shared__ float  s_rs[8], s_rq[8];

    const int tid   = threadIdx.x;
    const int plane = blockIdx.z;
    const int ty0   = blockIdx.y * 32;
    const int tx0   = blockIdx.x * 32;

    // ---- build coefficient table (uniform cubic B-spline, closed form) ----
    if (tid < 108) {
        const int m = tid / 9, k = tid % 9;
        float c0 = 0.f, c1 = 0.f, c2 = 0.f, c3 = 0.f;
        if (m < 11) {
            const float F[4][4] = {
                {1.f, -3.f,  3.f, -1.f},   // N_{m-3}
                {4.f,  0.f, -6.f,  3.f},   // N_{m-2}
                {1.f,  3.f,  3.f, -3.f},   // N_{m-1}
                {0.f,  0.f,  0.f,  1.f}    // N_{m}
            };
            const float sc = spline_scaler[k];
            #pragma unroll
            for (int r = 0; r < 4; r++) {
                int j = m - 3 + r;
                if (j >= 0 && j < 8) {
                    float w = spline_weight[k * 8 + j] * sc;
                    c0 += w * F[r][0]; c1 += w * F[r][1];
                    c2 += w * F[r][2]; c3 += w * F[r][3];
                }
            }
        }
        const float inv6 = 1.0f / 6.0f;
        __half2 h01 = __floats2half2_rn(c0 * inv6, c1 * inv6);
        __half2 h23 = __floats2half2_rn(c2 * inv6, c3 * inv6);
        uint2 w;
        w.x = *reinterpret_cast<unsigned*>(&h01);
        w.y = *reinterpret_cast<unsigned*>(&h23);
        s_coef[m * 9 + k] = w;
    }
    if (tid < 9) s_bw[tid] = base_weight[tid];

    // ---- load + transform halo tile (34x34), zero-padded outside plane ----
    const float* xp = x + plane * PLANE;
    for (int i = tid; i < 34 * 34; i += 256) {
        int hy = i / 34, hx = i % 34;
        int gy = ty0 + hy - 1, gx = tx0 + hx - 1;
        float v = (gy >= 0 && gy < Hn && gx >= 0 && gx < Wn) ? xp[gy * Wn + gx] : 0.0f;
        s_t[hy * 35 + hx] = kan_transform(v);
    }
    __syncthreads();

    // ---- compute 32x32 outputs (4 strided rows per thread) ----
    const int tx  = tid & 31;
    const int tyb = tid >> 5;
    float lsum = 0.f, lsq = 0.f;

    #pragma unroll
    for (int r = 0; r < 4; r++) {
        const int oy = tyb + r * 8;
        float acc = 0.f;
        #pragma unroll
        for (int dy = 0; dy < 3; dy++) {
            #pragma unroll
            for (int dx = 0; dx < 3; dx++) {
                const int k = dy * 3 + dx;
                float2 t = s_t[(oy + dy) * 35 + (tx + dx)];
                int   m = (int)t.y;
                float u = t.y - (float)m;
                uint2 cw = s_coef[m * 9 + k];
                float2 c01 = __half22float2(*reinterpret_cast<__half2*>(&cw.x));
                float2 c23 = __half22float2(*reinterpret_cast<__half2*>(&cw.y));
                float poly = fmaf(u, fmaf(u, fmaf(u, c23.y, c23.x), c01.y), c01.x);
                acc += poly + s_bw[k] * t.x;
            }
        }
        g_y[plane * PLANE + (ty0 + oy) * Wn + (tx0 + tx)] = acc;
        lsum += acc;
        lsq  = fmaf(acc, acc, lsq);
    }

    // ---- block reduction -> race-free partial slot (no atomics, no zeroing) ----
    #pragma unroll
    for (int o = 16; o > 0; o >>= 1) {
        lsum += __shfl_down_sync(0xffffffffu, lsum, o);
        lsq  += __shfl_down_sync(0xffffffffu, lsq,  o);
    }
    if (tx == 0) { s_rs[tyb] = lsum; s_rq[tyb] = lsq; }
    __syncthreads();
    if (tid == 0) {
        float s = 0.f, q = 0.f;
        #pragma unroll
        for (int i = 0; i < 8; i++) { s += s_rs[i]; q += s_rq[i]; }
        const int c = plane & (Cn - 1);
        const int b = plane >> 6;
        const int slot = c * NPART + b * 9 + blockIdx.y * 3 + blockIdx.x;
        g_psum[slot] = s;
        g_psq [slot] = q;
    }
}

// ---------------------------------------------------------------------------
// Kernel 2: BatchNorm (batch stats from partials) + ReLU
// grid = (3, 256 planes), block = 256; 3 float4 per thread.
// Stats computed redundantly per-warp via butterfly shuffle: no smem, no
// __syncthreads — warps are fully independent, pure latency-hidden stream.
// ---------------------------------------------------------------------------
__global__ __launch_bounds__(256)
void bn_relu_kernel(const float* __restrict__ gamma,
                    const float* __restrict__ beta,
                    float* __restrict__ out)
{
    const int plane = blockIdx.y;
    const int c     = plane & (Cn - 1);
    const int tid   = threadIdx.x;
    const int lane  = tid & 31;

    // issue the 3 independent data loads immediately
    const int base = plane * (PLANE / 4) + blockIdx.x * 768 + tid;
    float4 v0 = reinterpret_cast<const float4*>(g_y)[base];
    float4 v1 = reinterpret_cast<const float4*>(g_y)[base + 256];
    float4 v2 = reinterpret_cast<const float4*>(g_y)[base + 512];

    // per-warp redundant stats (36 partials, L2-broadcast)
    float s = g_psum[c * NPART + lane % NPART];   // lanes 0..31 -> j=lane
    float q = g_psq [c * NPART + lane % NPART];
    if (lane < NPART - 32) {                      // lanes 0..3 add j=lane+32
        s += g_psum[c * NPART + lane + 32];
        q += g_psq [c * NPART + lane + 32];
    }
    #pragma unroll
    for (int o = 16; o > 0; o >>= 1) {
        s += __shfl_xor_sync(0xffffffffu, s, o);
        q += __shfl_xor_sync(0xffffffffu, q, o);
    }

    const float invN = 1.0f / (float)CNT_PER_CH;
    float mean = s * invN;
    float var  = q * invN - mean * mean;
    float scl  = rsqrtf(var + BN_EPS) * gamma[c];
    float sh   = fmaf(-mean, scl, beta[c]);

    float4 o0, o1, o2;
    o0.x = fmaxf(fmaf(v0.x, scl, sh), 0.0f);
    o0.y = fmaxf(fmaf(v0.y, scl, sh), 0.0f);
    o0.z = fmaxf(fmaf(v0.z, scl, sh), 0.0f);
    o0.w = fmaxf(fmaf(v0.w, scl, sh), 0.0f);
    o1.x = fmaxf(fmaf(v1.x, scl, sh), 0.0f);
    o1.y = fmaxf(fmaf(v1.y, scl, sh), 0.0f);
    o1.z = fmaxf(fmaf(v1.z, scl, sh), 0.0f);
    o1.w = fmaxf(fmaf(v1.w, scl, sh), 0.0f);
    o2.x = fmaxf(fmaf(v2.x, scl, sh), 0.0f);
    o2.y = fmaxf(fmaf(v2.y, scl, sh), 0.0f);
    o2.z = fmaxf(fmaf(v2.z, scl, sh), 0.0f);
    o2.w = fmaxf(fmaf(v2.w, scl, sh), 0.0f);
    reinterpret_cast<float4*>(out)[base]       = o0;
    reinterpret_cast<float4*>(out)[base + 256] = o1;
    reinterpret_cast<float4*>(out)[base + 512] = o2;
}

// ---------------------------------------------------------------------------
extern "C" void kernel_launch(void* const* d_in, const int* in_sizes, int n_in,
                              void* d_out, int out_size)
{
    const float* x             = (const float*)d_in[0];
    const float* base_weight   = (const float*)d_in[1];
    const float* spline_weight = (const float*)d_in[2];
    const float* spline_scaler = (const float*)d_in[3];
    const float* bn_gamma      = (const float*)d_in[4];
    const float* bn_beta       = (const float*)d_in[5];
    float* out                 = (float*)d_out;

    dim3 grid(3, 3, NPLANES);
    kan_conv_kernel<<<grid, 256>>>(x, base_weight, spline_weight, spline_scaler);

    dim3 bgrid(3, NPLANES);   // 768 blocks, 3 float4 per thread
    bn_relu_kernel<<<bgrid, 256>>>(bn_gamma, bn_beta, out);
}